// round 1
// baseline (speedup 1.0000x reference)
#include <cuda_runtime.h>
#include <cstdint>

// Problem constants
#define NTOK 32768      // B*S = 8*4096
#define EDIM 512
#define FFN  2048
#define NW   4

// GEMM tiling
#define BM 128
#define BN 128
#define BK 32
#define KTILES (FFN / BK)          // 64
#define AS_STRIDE 36               // padded row stride (floats) -> conflict-free frags
#define BUF_ELEMS (128 * AS_STRIDE)
#define SMEM_BYTES (4 * BUF_ELEMS * 4)   // 2 A bufs + 2 B bufs = 73728 B

// Device scratch (allocation-free rule: __device__ globals)
__device__ float    g_meas[NTOK * NW];          // 512 KB
__device__ uint32_t g_w2t[EDIM * FFN];          // 4 MB, W2 pre-rounded to tf32

__device__ __forceinline__ uint32_t f2tf32(float f) {
    uint32_t u;
    asm("cvt.rna.tf32.f32 %0, %1;" : "=r"(u) : "f"(f));
    return u;
}

// ---------------------------------------------------------------------------
// Kernel 1: meas[n,w] = cos(theta_w) * cos(x[n,w])   (quantum circuit collapsed)
// ---------------------------------------------------------------------------
__global__ void meas_kernel(const float* __restrict__ x,
                            const float* __restrict__ theta) {
    int t = blockIdx.x * blockDim.x + threadIdx.x;
    if (t >= NTOK) return;
    float c0 = cosf(theta[0]), c1 = cosf(theta[1]);
    float c2 = cosf(theta[2]), c3 = cosf(theta[3]);
    float4 xv = *reinterpret_cast<const float4*>(x + (size_t)t * EDIM);
    float4 m;
    m.x = c0 * cosf(xv.x);
    m.y = c1 * cosf(xv.y);
    m.z = c2 * cosf(xv.z);
    m.w = c3 * cosf(xv.w);
    *reinterpret_cast<float4*>(g_meas + t * 4) = m;
}

// ---------------------------------------------------------------------------
// Kernel 2: round W2 to tf32 once (keeps CVT out of the GEMM hot loop)
// ---------------------------------------------------------------------------
__global__ void w2cvt_kernel(const float* __restrict__ W2) {
    int i = blockIdx.x * blockDim.x + threadIdx.x;
    if (i < EDIM * FFN) g_w2t[i] = f2tf32(W2[i]);
}

// ---------------------------------------------------------------------------
// Kernel 3: fused  out = relu(meas @ W1^T) @ W2^T
//   CTA tile: 128 (tokens) x 128 (E), K = FFN = 2048 in chunks of 32.
//   A chunk (H tile) computed on the fly in fp32 from meas (4 regs/thread) + W1,
//   relu'd, rounded to tf32, stored to padded SMEM. B chunk cp.async from g_w2t.
//   8 warps, each 64x32 via mma.sync.m16n8k8 tf32 (fp32 accumulate).
// ---------------------------------------------------------------------------
__global__ __launch_bounds__(256, 2)
void ffn_kernel(const float* __restrict__ W1, float* __restrict__ out) {
    extern __shared__ float smem_f[];
    uint32_t* As = reinterpret_cast<uint32_t*>(smem_f);              // 2 * BUF_ELEMS
    uint32_t* Bs = reinterpret_cast<uint32_t*>(smem_f) + 2 * BUF_ELEMS;

    const int tid  = threadIdx.x;
    const int lane = tid & 31;
    const int warp = tid >> 5;
    const int wm   = warp >> 2;   // 0..1  (64 rows each)
    const int wn   = warp & 3;    // 0..3  (32 cols each)
    const int mbase = blockIdx.y * BM;
    const int nbase = blockIdx.x * BN;

    // A-compute mapping: each thread owns (row ai, 16 consecutive k at ak0)
    const int ai  = tid >> 1;            // 0..127
    const int ak0 = (tid & 1) * 16;      // 0 or 16
    const float4 mv = *reinterpret_cast<const float4*>(g_meas + (size_t)(mbase + ai) * 4);

    float acc[4][4][4];
#pragma unroll
    for (int a = 0; a < 4; a++)
#pragma unroll
        for (int b = 0; b < 4; b++)
#pragma unroll
            for (int c = 0; c < 4; c++) acc[a][b][c] = 0.f;

    auto computeA = [&](int kt, int buf) {
        const float* w1p = W1 + (size_t)(kt * BK + ak0) * 4;
        uint32_t* dst = As + buf * BUF_ELEMS + ai * AS_STRIDE + ak0;
#pragma unroll
        for (int k = 0; k < 16; k += 4) {
            uint32_t v[4];
#pragma unroll
            for (int j = 0; j < 4; j++) {
                float4 w = *reinterpret_cast<const float4*>(w1p + (k + j) * 4);
                float h = fmaf(mv.x, w.x, fmaf(mv.y, w.y, fmaf(mv.z, w.z, mv.w * w.w)));
                v[j] = f2tf32(fmaxf(h, 0.f));
            }
            *reinterpret_cast<uint4*>(dst + k) = make_uint4(v[0], v[1], v[2], v[3]);
        }
    };

    auto loadB = [&](int kt, int buf) {
#pragma unroll
        for (int q = 0; q < 4; q++) {
            int f  = tid + q * 256;       // 0..1023 float4 slots
            int n  = f >> 3;              // 0..127 (E row within tile)
            int kq = f & 7;               // 0..7  (float4 within K chunk)
            const uint32_t* src = g_w2t + (size_t)(nbase + n) * FFN + kt * BK + kq * 4;
            uint32_t* dst = Bs + buf * BUF_ELEMS + n * AS_STRIDE + kq * 4;
            unsigned ds = (unsigned)__cvta_generic_to_shared(dst);
            asm volatile("cp.async.cg.shared.global [%0], [%1], 16;\n" :: "r"(ds), "l"(src));
        }
        asm volatile("cp.async.commit_group;\n");
    };

    // Prologue
    computeA(0, 0);
    loadB(0, 0);

    for (int kt = 0; kt < KTILES; kt++) {
        asm volatile("cp.async.wait_group 0;\n");
        __syncthreads();
        const int buf = kt & 1;
        if (kt + 1 < KTILES) {
            loadB(kt + 1, buf ^ 1);
            computeA(kt + 1, buf ^ 1);
        }
        const uint32_t* Ab = As + buf * BUF_ELEMS;
        const uint32_t* Bb = Bs + buf * BUF_ELEMS;
#pragma unroll
        for (int ks = 0; ks < 4; ks++) {
            uint32_t afr[4][4];
#pragma unroll
            for (int mt = 0; mt < 4; mt++) {
                int r = wm * 64 + mt * 16 + (lane >> 2);
                int c = ks * 8 + (lane & 3);
                const uint32_t* p = Ab + r * AS_STRIDE + c;
                afr[mt][0] = p[0];
                afr[mt][1] = p[8 * AS_STRIDE];
                afr[mt][2] = p[4];
                afr[mt][3] = p[8 * AS_STRIDE + 4];
            }
            uint32_t bfr[4][2];
#pragma unroll
            for (int nt = 0; nt < 4; nt++) {
                int n  = wn * 32 + nt * 8 + (lane >> 2);
                int kk = ks * 8 + (lane & 3);
                const uint32_t* p = Bb + n * AS_STRIDE + kk;
                bfr[nt][0] = p[0];
                bfr[nt][1] = p[4];
            }
#pragma unroll
            for (int mt = 0; mt < 4; mt++)
#pragma unroll
                for (int nt = 0; nt < 4; nt++) {
                    float* d = acc[mt][nt];
                    asm volatile(
                        "mma.sync.aligned.m16n8k8.row.col.f32.tf32.tf32.f32 "
                        "{%0,%1,%2,%3}, {%4,%5,%6,%7}, {%8,%9}, {%0,%1,%2,%3};\n"
                        : "+f"(d[0]), "+f"(d[1]), "+f"(d[2]), "+f"(d[3])
                        : "r"(afr[mt][0]), "r"(afr[mt][1]), "r"(afr[mt][2]), "r"(afr[mt][3]),
                          "r"(bfr[nt][0]), "r"(bfr[nt][1]));
                }
        }
    }

    // Epilogue: fp32 stores, float2 per (row, col-pair)
#pragma unroll
    for (int mt = 0; mt < 4; mt++) {
        int r0 = mbase + wm * 64 + mt * 16 + (lane >> 2);
#pragma unroll
        for (int nt = 0; nt < 4; nt++) {
            int c0 = nbase + wn * 32 + nt * 8 + (lane & 3) * 2;
            float2 v0 = make_float2(acc[mt][nt][0], acc[mt][nt][1]);
            float2 v1 = make_float2(acc[mt][nt][2], acc[mt][nt][3]);
            *reinterpret_cast<float2*>(out + (size_t)r0 * EDIM + c0)       = v0;
            *reinterpret_cast<float2*>(out + (size_t)(r0 + 8) * EDIM + c0) = v1;
        }
    }
}

// ---------------------------------------------------------------------------
extern "C" void kernel_launch(void* const* d_in, const int* in_sizes, int n_in,
                              void* d_out, int out_size) {
    const float* x     = (const float*)d_in[0];
    const float* theta = (const float*)d_in[1];
    const float* W1    = (const float*)d_in[2];
    const float* W2    = (const float*)d_in[3];
    float* out = (float*)d_out;

    // Idempotent, called every time (no static guards).
    cudaFuncSetAttribute(ffn_kernel, cudaFuncAttributeMaxDynamicSharedMemorySize, SMEM_BYTES);

    meas_kernel<<<NTOK / 256, 256>>>(x, theta);
    w2cvt_kernel<<<(EDIM * FFN) / 256, 256>>>(W2);

    dim3 grid(EDIM / BN, NTOK / BM);   // (4, 256)
    ffn_kernel<<<grid, 256, SMEM_BYTES>>>(W1, out);
}

// round 4
// speedup vs baseline: 1.2360x; 1.2360x over previous
#include <cuda_runtime.h>
#include <cuda_fp16.h>
#include <cstdint>

// ---------------------------------------------------------------------------
// QFeedForward: out = relu( (cos(theta)*cos(x[...,:4])) @ W1^T ) @ W2^T
// Legacy-path fp16 mma.sync.m16n8k16 (compute_100 target: no tcgen05).
// GEMM M=32768, N=512, K=2048. CTA tile 128x128, K-chunk 64, double-buffered
// SW128 SMEM, ldmatrix fragment loads, fp32 accumulate.
// ---------------------------------------------------------------------------

#define NTOK 32768
#define EDIM 512
#define FFN  2048

#define BM 128
#define BN 128
#define BK 64
#define KTILES (FFN / BK)            // 32

#define SM_ABUF 16384                // 128 rows x 128B (64 halfs), SW128
#define SM_BBUF 16384
#define SM_B0   (2 * SM_ABUF)
#define SMEM_TOTAL (2 * SM_ABUF + 2 * SM_BBUF)   // 65536 -> 2 CTAs/SM

__device__ __half g_w2h[EDIM * FFN];   // W2 pre-rounded to fp16 (2 MB)

__device__ __forceinline__ uint32_t smem_u32(const void* p) {
    uint32_t a;
    asm("{ .reg .u64 t; cvta.to.shared.u64 t, %1; cvt.u32.u64 %0, t; }" : "=r"(a) : "l"(p));
    return a;
}

// ---------------------------------------------------------------------------
// W2 -> fp16 (one float4 -> 8 bytes per thread)
// ---------------------------------------------------------------------------
__global__ void w2cvt_kernel(const float* __restrict__ W2) {
    int i = blockIdx.x * blockDim.x + threadIdx.x;   // float4 index
    float4 v = reinterpret_cast<const float4*>(W2)[i];
    __half2 a = __floats2half2_rn(v.x, v.y);
    __half2 b = __floats2half2_rn(v.z, v.w);
    reinterpret_cast<__half2*>(g_w2h)[i * 2 + 0] = a;
    reinterpret_cast<__half2*>(g_w2h)[i * 2 + 1] = b;
}

// ---------------------------------------------------------------------------
// Fused FFN kernel
// ---------------------------------------------------------------------------
__global__ __launch_bounds__(256, 2)
void ffn_kernel(const float* __restrict__ x, const float* __restrict__ theta,
                const float* __restrict__ W1, float* __restrict__ out)
{
    extern __shared__ char smem[];
    const uint32_t sbase = smem_u32(smem);
    const int tid  = threadIdx.x;
    const int lane = tid & 31;
    const int warp = tid >> 5;
    const int wm   = warp >> 2;     // 0..1  (64 rows)
    const int wn   = warp & 3;      // 0..3  (32 cols)
    const int mbase = blockIdx.y * BM;
    const int nbase = blockIdx.x * BN;

    // Quantum circuit collapsed: mv[w] = cos(theta_w) * cos(x[row, w]).
    // Thread t owns A row (t>>1), K half (t&1)*32 within each chunk.
    const int arow = tid >> 1;
    const int ak0  = (tid & 1) * 32;
    float4 xv = *reinterpret_cast<const float4*>(x + (size_t)(mbase + arow) * EDIM);
    float4 mv;
    mv.x = cosf(theta[0]) * cosf(xv.x);
    mv.y = cosf(theta[1]) * cosf(xv.y);
    mv.z = cosf(theta[2]) * cosf(xv.z);
    mv.w = cosf(theta[3]) * cosf(xv.w);

    float acc[4][4][4];
#pragma unroll
    for (int a = 0; a < 4; a++)
#pragma unroll
        for (int b = 0; b < 4; b++)
#pragma unroll
            for (int c = 0; c < 4; c++) acc[a][b][c] = 0.f;

    // A producer: H[row,k] = relu(mv . W1[k]) in fp16, SW128 layout
    auto computeA = [&](int kt, int buf) {
        const float4* w1p = reinterpret_cast<const float4*>(W1) + kt * BK + ak0;
        char* abase = smem + buf * SM_ABUF;
        const uint32_t swrow = ((uint32_t)arow & 7u) << 4;
        const uint32_t rb = (uint32_t)arow * 128u;
#pragma unroll
        for (int j = 0; j < 32; j += 8) {
            uint32_t v[4];
#pragma unroll
            for (int q = 0; q < 4; q++) {
                float4 wa = w1p[j + 2 * q];
                float4 wb = w1p[j + 2 * q + 1];
                float h0 = fmaf(mv.x, wa.x, fmaf(mv.y, wa.y, fmaf(mv.z, wa.z, mv.w * wa.w)));
                float h1 = fmaf(mv.x, wb.x, fmaf(mv.y, wb.y, fmaf(mv.z, wb.z, mv.w * wb.w)));
                __half2 hh = __floats2half2_rn(fmaxf(h0, 0.f), fmaxf(h1, 0.f));
                v[q] = *reinterpret_cast<uint32_t*>(&hh);
            }
            uint32_t c = (uint32_t)(ak0 + j) * 2u;          // byte col, mult of 16
            *reinterpret_cast<uint4*>(abase + rb + (c ^ swrow)) =
                make_uint4(v[0], v[1], v[2], v[3]);
        }
    };

    // B tile: 128 rows(n) x 64 halfs (128B), cp.async 16B chunks, SW128
    auto loadB = [&](int kt, int buf) {
        char* bb = smem + SM_B0 + buf * SM_BBUF;
#pragma unroll
        for (int q = 0; q < 4; q++) {
            int f  = tid + q * 256;        // 0..1023 16B slots
            int n  = f >> 3, kq = f & 7;
            const __half* src = g_w2h + (size_t)(nbase + n) * FFN + kt * BK + kq * 8;
            uint32_t c  = (uint32_t)kq * 16u;
            uint32_t ds = (uint32_t)__cvta_generic_to_shared(bb) + (uint32_t)n * 128u +
                          (c ^ (((uint32_t)n & 7u) << 4));
            asm volatile("cp.async.cg.shared.global [%0], [%1], 16;" :: "r"(ds), "l"(src));
        }
        asm volatile("cp.async.commit_group;");
    };

    // ldmatrix per-lane address components (r&7 == lane&7 for all tiles)
    const uint32_t swl   = ((uint32_t)lane & 7u) << 4;
    const int rlo  = ((lane >> 3) & 1) * 8 + (lane & 7);   // row-within-16 for A
    const int akb  = ((lane >> 4) & 1) * 16;               // k-byte half for A
    const int nlo  = ((lane >> 4) & 1) * 8 + (lane & 7);   // row-within-16 for B
    const int bkb  = ((lane >> 3) & 1) * 16;               // k-byte half for B

    // Prologue
    computeA(0, 0);
    loadB(0, 0);

    for (int kt = 0; kt < KTILES; kt++) {
        asm volatile("cp.async.wait_group 0;");
        __syncthreads();
        const int buf = kt & 1;
        if (kt + 1 < KTILES) {
            loadB(kt + 1, buf ^ 1);
            computeA(kt + 1, buf ^ 1);
        }
        const uint32_t Ab = sbase + buf * SM_ABUF;
        const uint32_t Bb = sbase + SM_B0 + buf * SM_BBUF;
#pragma unroll
        for (int ks = 0; ks < 4; ks++) {
            uint32_t afr[4][4];
#pragma unroll
            for (int mt = 0; mt < 4; mt++) {
                int r = wm * 64 + mt * 16 + rlo;
                uint32_t addr = Ab + (uint32_t)r * 128u +
                                (uint32_t)((ks * 32 + akb)) ^ 0u;  // xor applied below
                addr = Ab + (uint32_t)r * 128u + (((uint32_t)(ks * 32 + akb)) ^ swl);
                asm volatile("ldmatrix.sync.aligned.m8n8.x4.shared.b16 {%0,%1,%2,%3}, [%4];"
                             : "=r"(afr[mt][0]), "=r"(afr[mt][1]),
                               "=r"(afr[mt][2]), "=r"(afr[mt][3]) : "r"(addr));
            }
            uint32_t bfr[4][2];
#pragma unroll
            for (int nt2 = 0; nt2 < 2; nt2++) {
                int n = wn * 32 + nt2 * 16 + nlo;
                uint32_t addr = Bb + (uint32_t)n * 128u +
                                (((uint32_t)(ks * 32 + bkb)) ^ swl);
                asm volatile("ldmatrix.sync.aligned.m8n8.x4.shared.b16 {%0,%1,%2,%3}, [%4];"
                             : "=r"(bfr[nt2 * 2][0]),     "=r"(bfr[nt2 * 2][1]),
                               "=r"(bfr[nt2 * 2 + 1][0]), "=r"(bfr[nt2 * 2 + 1][1]) : "r"(addr));
            }
#pragma unroll
            for (int mt = 0; mt < 4; mt++)
#pragma unroll
                for (int nt = 0; nt < 4; nt++) {
                    float* d = acc[mt][nt];
                    asm volatile(
                        "mma.sync.aligned.m16n8k16.row.col.f32.f16.f16.f32 "
                        "{%0,%1,%2,%3}, {%4,%5,%6,%7}, {%8,%9}, {%0,%1,%2,%3};"
                        : "+f"(d[0]), "+f"(d[1]), "+f"(d[2]), "+f"(d[3])
                        : "r"(afr[mt][0]), "r"(afr[mt][1]), "r"(afr[mt][2]), "r"(afr[mt][3]),
                          "r"(bfr[nt][0]), "r"(bfr[nt][1]));
                }
        }
    }

    // Epilogue: fp32 stores
#pragma unroll
    for (int mt = 0; mt < 4; mt++) {
        int r0 = mbase + wm * 64 + mt * 16 + (lane >> 2);
#pragma unroll
        for (int nt = 0; nt < 4; nt++) {
            int c0 = nbase + wn * 32 + nt * 8 + (lane & 3) * 2;
            *reinterpret_cast<float2*>(out + (size_t)r0 * EDIM + c0) =
                make_float2(acc[mt][nt][0], acc[mt][nt][1]);
            *reinterpret_cast<float2*>(out + (size_t)(r0 + 8) * EDIM + c0) =
                make_float2(acc[mt][nt][2], acc[mt][nt][3]);
        }
    }
}

// ---------------------------------------------------------------------------
extern "C" void kernel_launch(void* const* d_in, const int* in_sizes, int n_in,
                              void* d_out, int out_size) {
    const float* x     = (const float*)d_in[0];
    const float* theta = (const float*)d_in[1];
    const float* W1    = (const float*)d_in[2];
    const float* W2    = (const float*)d_in[3];
    float* out = (float*)d_out;

    cudaFuncSetAttribute(ffn_kernel, cudaFuncAttributeMaxDynamicSharedMemorySize, SMEM_TOTAL);

    w2cvt_kernel<<<(EDIM * FFN / 4) / 256, 256>>>(W2);

    dim3 grid(EDIM / BN, NTOK / BM);   // (4, 256)
    ffn_kernel<<<grid, 256, SMEM_TOTAL>>>(x, theta, W1, out);
}

// round 7
// speedup vs baseline: 1.6147x; 1.3064x over previous
#include <cuda_runtime.h>
#include <cuda_fp16.h>
#include <cstdint>

// ---------------------------------------------------------------------------
// QFeedForward: out = relu( (cos(theta)*cos(x[...,:4])) @ W1^T ) @ W2^T
// fp16 mma.sync.m16n8k16 (compute_100 target: no tcgen05 available).
// GEMM M=32768, N=512, K=2048. CTA tile 128x128, 4 warps of 64x64 each,
// 128 threads/CTA, 2 CTAs/SM. K-chunk 64, double-buffered SW128 SMEM,
// ldmatrix.x4 fragment loads, fp32 accumulate.
// ---------------------------------------------------------------------------

#define NTOK 32768
#define EDIM 512
#define FFN  2048

#define BM 128
#define BN 128
#define BK 64
#define KTILES (FFN / BK)            // 32
#define NTHREADS 128

#define SM_ABUF 16384                // 128 rows x 128B (64 halfs), SW128
#define SM_BBUF 16384                // 128 rows x 128B
#define SM_B0   (2 * SM_ABUF)
#define SMEM_TOTAL (2 * SM_ABUF + 2 * SM_BBUF)   // 65536 B -> 2 CTAs/SM

__device__ __half g_w2h[EDIM * FFN];   // W2 pre-rounded to fp16 (2 MB)

__device__ __forceinline__ uint32_t smem_u32(const void* p) {
    uint32_t a;
    asm("{ .reg .u64 t; cvta.to.shared.u64 t, %1; cvt.u32.u64 %0, t; }" : "=r"(a) : "l"(p));
    return a;
}

// ---------------------------------------------------------------------------
// W2 -> fp16 (one float4 -> 8 bytes per thread)
// ---------------------------------------------------------------------------
__global__ void w2cvt_kernel(const float* __restrict__ W2) {
    int i = blockIdx.x * blockDim.x + threadIdx.x;   // float4 index
    float4 v = reinterpret_cast<const float4*>(W2)[i];
    __half2 a = __floats2half2_rn(v.x, v.y);
    __half2 b = __floats2half2_rn(v.z, v.w);
    reinterpret_cast<__half2*>(g_w2h)[i * 2 + 0] = a;
    reinterpret_cast<__half2*>(g_w2h)[i * 2 + 1] = b;
}

// ---------------------------------------------------------------------------
// Fused FFN kernel
// ---------------------------------------------------------------------------
__global__ __launch_bounds__(NTHREADS, 2)
void ffn_kernel(const float* __restrict__ x, const float* __restrict__ theta,
                const float* __restrict__ W1, float* __restrict__ out)
{
    extern __shared__ char smem[];
    const uint32_t sbase = smem_u32(smem);
    const int tid  = threadIdx.x;
    const int lane = tid & 31;
    const int warp = tid >> 5;      // 0..3
    const int wm   = warp >> 1;     // 0..1  (64 rows)
    const int wn   = warp & 1;      // 0..1  (64 cols)
    const int mbase = blockIdx.y * BM;
    const int nbase = blockIdx.x * BN;

    // Quantum circuit collapsed: mv[w] = cos(theta_w) * cos(x[row, w]).
    // Thread t owns A row t (all 64 k of each chunk).
    const int arow = tid;
    float4 xv = *reinterpret_cast<const float4*>(x + (size_t)(mbase + arow) * EDIM);
    float4 mv;
    mv.x = cosf(theta[0]) * cosf(xv.x);
    mv.y = cosf(theta[1]) * cosf(xv.y);
    mv.z = cosf(theta[2]) * cosf(xv.z);
    mv.w = cosf(theta[3]) * cosf(xv.w);

    float acc[4][8][4];
#pragma unroll
    for (int a = 0; a < 4; a++)
#pragma unroll
        for (int b = 0; b < 8; b++)
#pragma unroll
            for (int c = 0; c < 4; c++) acc[a][b][c] = 0.f;

    // A producer: H[row,k] = relu(mv . W1[k]) in fp16, SW128 layout.
    // One thread per row; 64 k values -> 8 x STS.128.
    auto computeA = [&](int kt, int buf) {
        const float4* w1p = reinterpret_cast<const float4*>(W1) + kt * BK;
        char* abase = smem + buf * SM_ABUF;
        const uint32_t swrow = ((uint32_t)arow & 7u) << 4;
        const uint32_t rb = (uint32_t)arow * 128u;
#pragma unroll
        for (int j = 0; j < 64; j += 8) {
            uint32_t v[4];
#pragma unroll
            for (int q = 0; q < 4; q++) {
                float4 wa = w1p[j + 2 * q];
                float4 wb = w1p[j + 2 * q + 1];
                float h0 = fmaf(mv.x, wa.x, fmaf(mv.y, wa.y, fmaf(mv.z, wa.z, mv.w * wa.w)));
                float h1 = fmaf(mv.x, wb.x, fmaf(mv.y, wb.y, fmaf(mv.z, wb.z, mv.w * wb.w)));
                __half2 hh = __floats2half2_rn(fmaxf(h0, 0.f), fmaxf(h1, 0.f));
                v[q] = *reinterpret_cast<uint32_t*>(&hh);
            }
            uint32_t c = (uint32_t)j * 2u;                  // byte col, mult of 16
            *reinterpret_cast<uint4*>(abase + rb + (c ^ swrow)) =
                make_uint4(v[0], v[1], v[2], v[3]);
        }
    };

    // B tile: 128 rows(n) x 64 halfs (128B rows), cp.async 16B chunks, SW128
    auto loadB = [&](int kt, int buf) {
        char* bb = smem + SM_B0 + buf * SM_BBUF;
#pragma unroll
        for (int q = 0; q < 8; q++) {
            int f  = tid + q * NTHREADS;   // 0..1023 16B slots
            int n  = f >> 3, kq = f & 7;
            const __half* src = g_w2h + (size_t)(nbase + n) * FFN + kt * BK + kq * 8;
            uint32_t c  = (uint32_t)kq * 16u;
            uint32_t ds = (uint32_t)__cvta_generic_to_shared(bb) + (uint32_t)n * 128u +
                          (c ^ (((uint32_t)n & 7u) << 4));
            asm volatile("cp.async.cg.shared.global [%0], [%1], 16;" :: "r"(ds), "l"(src));
        }
        asm volatile("cp.async.commit_group;");
    };

    // ldmatrix per-lane address components (r&7 == lane&7 for all tiles)
    const uint32_t swl = ((uint32_t)lane & 7u) << 4;
    const int rlo = ((lane >> 3) & 1) * 8 + (lane & 7);   // row-within-16 for A
    const int akb = ((lane >> 4) & 1) * 16;               // k-byte half for A
    const int nlo = ((lane >> 4) & 1) * 8 + (lane & 7);   // row-within-16 for B
    const int bkb = ((lane >> 3) & 1) * 16;               // k-byte half for B

    // Prologue
    computeA(0, 0);
    loadB(0, 0);

    for (int kt = 0; kt < KTILES; kt++) {
        asm volatile("cp.async.wait_group 0;");
        __syncthreads();
        const int buf = kt & 1;
        if (kt + 1 < KTILES) {
            loadB(kt + 1, buf ^ 1);
            computeA(kt + 1, buf ^ 1);
        }
        const uint32_t Ab = sbase + buf * SM_ABUF;
        const uint32_t Bb = sbase + SM_B0 + buf * SM_BBUF;
#pragma unroll
        for (int ks = 0; ks < 4; ks++) {
            uint32_t afr[4][4];
#pragma unroll
            for (int mt = 0; mt < 4; mt++) {
                int r = wm * 64 + mt * 16 + rlo;
                uint32_t addr = Ab + (uint32_t)r * 128u + (((uint32_t)(ks * 32 + akb)) ^ swl);
                asm volatile("ldmatrix.sync.aligned.m8n8.x4.shared.b16 {%0,%1,%2,%3}, [%4];"
                             : "=r"(afr[mt][0]), "=r"(afr[mt][1]),
                               "=r"(afr[mt][2]), "=r"(afr[mt][3]) : "r"(addr));
            }
            uint32_t bfr[8][2];
#pragma unroll
            for (int nt2 = 0; nt2 < 4; nt2++) {
                int n = wn * 64 + nt2 * 16 + nlo;
                uint32_t addr = Bb + (uint32_t)n * 128u + (((uint32_t)(ks * 32 + bkb)) ^ swl);
                asm volatile("ldmatrix.sync.aligned.m8n8.x4.shared.b16 {%0,%1,%2,%3}, [%4];"
                             : "=r"(bfr[nt2 * 2][0]),     "=r"(bfr[nt2 * 2][1]),
                               "=r"(bfr[nt2 * 2 + 1][0]), "=r"(bfr[nt2 * 2 + 1][1]) : "r"(addr));
            }
#pragma unroll
            for (int mt = 0; mt < 4; mt++)
#pragma unroll
                for (int nt = 0; nt < 8; nt++) {
                    float* d = acc[mt][nt];
                    asm volatile(
                        "mma.sync.aligned.m16n8k16.row.col.f32.f16.f16.f32 "
                        "{%0,%1,%2,%3}, {%4,%5,%6,%7}, {%8,%9}, {%0,%1,%2,%3};"
                        : "+f"(d[0]), "+f"(d[1]), "+f"(d[2]), "+f"(d[3])
                        : "r"(afr[mt][0]), "r"(afr[mt][1]), "r"(afr[mt][2]), "r"(afr[mt][3]),
                          "r"(bfr[nt][0]), "r"(bfr[nt][1]));
                }
        }
    }

    // Epilogue: fp32 stores
#pragma unroll
    for (int mt = 0; mt < 4; mt++) {
        int r0 = mbase + wm * 64 + mt * 16 + (lane >> 2);
#pragma unroll
        for (int nt = 0; nt < 8; nt++) {
            int c0 = nbase + wn * 64 + nt * 8 + (lane & 3) * 2;
            *reinterpret_cast<float2*>(out + (size_t)r0 * EDIM + c0) =
                make_float2(acc[mt][nt][0], acc[mt][nt][1]);
            *reinterpret_cast<float2*>(out + (size_t)(r0 + 8) * EDIM + c0) =
                make_float2(acc[mt][nt][2], acc[mt][nt][3]);
        }
    }
}

// ---------------------------------------------------------------------------
extern "C" void kernel_launch(void* const* d_in, const int* in_sizes, int n_in,
                              void* d_out, int out_size) {
    const float* x     = (const float*)d_in[0];
    const float* theta = (const float*)d_in[1];
    const float* W1    = (const float*)d_in[2];
    const float* W2    = (const float*)d_in[3];
    float* out = (float*)d_out;

    cudaFuncSetAttribute(ffn_kernel, cudaFuncAttributeMaxDynamicSharedMemorySize, SMEM_TOTAL);

    w2cvt_kernel<<<(EDIM * FFN / 4) / 256, 256>>>(W2);

    dim3 grid(EDIM / BN, NTOK / BM);   // (4, 256)
    ffn_kernel<<<grid, NTHREADS, SMEM_TOTAL>>>(x, theta, W1, out);
}